// round 14
// baseline (speedup 1.0000x reference)
#include <cuda_runtime.h>
#include <math.h>
#include <float.h>

#define NTOT 16384
#define NT2  (2 * NTOT)
#define BB 64
#define NN 256
#define IND 7
#define HID 64
#define OUTD 32
#define EE 524288
#define ADJ 96
#define NEL 65536
#define SPLIT 8
#define SCAT_BLOCKS (2 * EE / 256)
#define LIN1_BLOCKS (NT2 * HID / 256)

typedef unsigned long long ull;

// ---------------- scratch ----------------
__device__ float g_xl[NT2 * HID];
__device__ float g_xr[NT2 * HID];
__device__ float g_h[NT2 * HID];
__device__ float g_xl2[NT2 * OUTD];
__device__ float g_xr2[NT2 * OUTD];
__device__ float g_ho[NT2 * OUTD];
__device__ float g_sl1[NT2], g_sr1[NT2];     // att1 . xl / xr per node
__device__ float g_sl2[NT2], g_sr2[NT2];     // att2 . xl2 / xr2 per node
__device__ int g_cnt[NT2];
__device__ int g_adj[NT2 * ADJ];
__device__ float g_sim[BB * NEL];
__device__ float g_E[BB * NEL];              // exp(-d) cache for Sinkhorn
__device__ float g_sum[BB], g_sumsq[BB];
__device__ unsigned g_minkey[BB], g_maxkey[BB];
__device__ float g_S[5][BB];
__device__ int g_arr[5][BB];
__device__ int g_is64;

// ---------------- helpers ----------------
__device__ __forceinline__ unsigned f2key(float f) {
    unsigned u = __float_as_uint(f);
    return (u & 0x80000000u) ? ~u : (u | 0x80000000u);
}
__device__ __forceinline__ float key2f(unsigned k) {
    unsigned u = (k & 0x80000000u) ? (k ^ 0x80000000u) : ~k;
    return __uint_as_float(u);
}
__device__ __forceinline__ ull ffma2(ull a, ull b, ull c) {
    ull d;
    asm("fma.rn.f32x2 %0, %1, %2, %3;" : "=l"(d) : "l"(a), "l"(b), "l"(c));
    return d;
}
__device__ __forceinline__ ull bcast2(float x) {
    ull d;
    asm("mov.b64 %0, {%1, %1};" : "=l"(d) : "f"(x));
    return d;
}

// ---------------- setup ----------------
__global__ void setup_kernel(const int* __restrict__ e1w) {
    int t = blockIdx.x * blockDim.x + threadIdx.x;
    if (t < NT2) {
        g_cnt[t] = 1;
        g_adj[t * ADJ] = t;   // self loop first
    }
    if (t < BB) {
        g_sum[t] = 0.f;
        g_sumsq[t] = 0.f;
        g_minkey[t] = 0xFFFFFFFFu;
        g_maxkey[t] = 0u;
#pragma unroll
        for (int u = 0; u < 5; u++) { g_S[u][t] = 0.f; g_arr[u][t] = 0; }
    }
    if (t == 0) {
        int any = 0;
#pragma unroll
        for (int i = 0; i < 64; i++) any |= e1w[2 * i + 1];
        g_is64 = (any == 0) ? 1 : 0;
    }
}

// ---------------- scatter + lin1 + layer-1 node scores (fused) ------------
__global__ void scatlin_kernel(const void* __restrict__ e1, const void* __restrict__ e2,
                               const float* __restrict__ x1, const float* __restrict__ x2,
                               const float* __restrict__ Wl, const float* __restrict__ Wr,
                               const float* __restrict__ bl, const float* __restrict__ br,
                               const float* __restrict__ att) {
    __shared__ float sp[8], sq[8];
    int gb = blockIdx.x;
    int tid = threadIdx.x;
    if (gb < SCAT_BLOCKS) {
        int e = gb * 256 + tid;
        int side = (e >= EE);
        int le = e - side * EE;
        const void* ep = side ? e2 : e1;
        int src, dst;
        if (g_is64) {
            const long long* p = (const long long*)ep;
            src = (int)p[le];
            dst = (int)p[EE + le];
        } else {
            const int* p = (const int*)ep;
            src = p[le];
            dst = p[EE + le];
        }
        int n = side * NTOT + dst;
        int pos = atomicAdd(&g_cnt[n], 1);
        if (pos < ADJ) g_adj[n * ADJ + pos] = side * NTOT + src;
    } else {
        int gid = (gb - SCAT_BLOCKS) * 256 + tid;   // block covers 4 whole nodes
        int n = gid >> 6, d = gid & 63;
        const float* x = (n >= NTOT) ? (x2 + (n - NTOT) * IND) : (x1 + n * IND);
        float a = bl[d], b = br[d];
#pragma unroll
        for (int k = 0; k < IND; k++) {
            float xv = x[k];
            a = fmaf(xv, Wl[k * HID + d], a);
            b = fmaf(xv, Wr[k * HID + d], b);
        }
        g_xl[gid] = a;
        g_xr[gid] = b;
        // node scores: att . xl, att . xr (node spans 2 warps)
        float atd = att[d];
        float pa = atd * a, pb = atd * b;
#pragma unroll
        for (int o = 16; o > 0; o >>= 1) {
            pa += __shfl_xor_sync(0xffffffffu, pa, o);
            pb += __shfl_xor_sync(0xffffffffu, pb, o);
        }
        int w = tid >> 5;
        if ((tid & 31) == 0) { sp[w] = pa; sq[w] = pb; }
        __syncthreads();
        if (tid < 4) {
            int nb = ((gb - SCAT_BLOCKS) * 256) >> 6;
            g_sl1[nb + tid] = sp[2 * tid] + sp[2 * tid + 1];
            g_sr1[nb + tid] = sq[2 * tid] + sq[2 * tid + 1];
        }
    }
}

// ---------------- GATv2 with separable score: 0.6(sl+sr) + 0.4 att.|v| ----
__device__ __forceinline__ float absdot8(float4 a0, float4 a1, float4 xr0, float4 xr1,
                                         float4 at0, float4 at1) {
    float q = at0.x * fabsf(a0.x + xr0.x);
    q = fmaf(at0.y, fabsf(a0.y + xr0.y), q);
    q = fmaf(at0.z, fabsf(a0.z + xr0.z), q);
    q = fmaf(at0.w, fabsf(a0.w + xr0.w), q);
    q = fmaf(at1.x, fabsf(a1.x + xr1.x), q);
    q = fmaf(at1.y, fabsf(a1.y + xr1.y), q);
    q = fmaf(at1.z, fabsf(a1.z + xr1.z), q);
    q = fmaf(at1.w, fabsf(a1.w + xr1.w), q);
    return q;
}

template <int D, int LANES, bool RELU>
__device__ __forceinline__ void gat_body(const float* __restrict__ xl,
                                         const float* __restrict__ xr,
                                         const float* __restrict__ sl,
                                         const float* __restrict__ sr,
                                         const float* __restrict__ att,
                                         const float* __restrict__ bias,
                                         float* __restrict__ out) {
    constexpr int GP = 32 / LANES;
    int warp = (blockIdx.x * blockDim.x + threadIdx.x) >> 5;
    int lane = threadIdx.x & 31;
    int sub = lane / LANES;
    int l = lane % LANES;
    int n = warp * GP + sub;
    if (n >= NT2) return;
    unsigned gmask = ((1u << LANES) - 1u) << (sub * LANES);

    const float* xlb = xl + l * 8;
    const float* xrb = xr + n * D + l * 8;
    float4 xr0 = *(const float4*)(xrb);
    float4 xr1 = *(const float4*)(xrb + 4);
    float4 at0 = *(const float4*)(att + l * 8);
    float4 at1 = *(const float4*)(att + l * 8 + 4);
    float srn = sr[n];

    // self loop (score shift reference)
    float4 s0 = *(const float4*)(xlb + n * D);
    float4 s1 = *(const float4*)(xlb + n * D + 4);
    float q = absdot8(s0, s1, xr0, xr1, at0, at1);
#pragma unroll
    for (int o = LANES / 2; o > 0; o >>= 1) q += __shfl_xor_sync(gmask, q, o);
    float pself = fmaf(0.4f, q, 0.6f * (sl[n] + srn));

    float4 accA0 = s0, accA1 = s1; float denA = 1.f;
    float4 accB0 = make_float4(0.f, 0.f, 0.f, 0.f), accB1 = accB0; float denB = 0.f;

    int cnt = g_cnt[n];
    if (cnt > ADJ) cnt = ADJ;
    const int* colp = g_adj + n * ADJ;
    int j = 1;
    for (; j + 1 < cnt; j += 2) {
        int sA = colp[j], sB = colp[j + 1];
        float slA = sl[sA], slB = sl[sB];
        float4 a0 = *(const float4*)(xlb + sA * D);
        float4 a1 = *(const float4*)(xlb + sA * D + 4);
        float4 b0 = *(const float4*)(xlb + sB * D);
        float4 b1 = *(const float4*)(xlb + sB * D + 4);
        float qA = absdot8(a0, a1, xr0, xr1, at0, at1);
        float qB = absdot8(b0, b1, xr0, xr1, at0, at1);
#pragma unroll
        for (int o = LANES / 2; o > 0; o >>= 1) {
            qA += __shfl_xor_sync(gmask, qA, o);
            qB += __shfl_xor_sync(gmask, qB, o);
        }
        float pA = fmaf(0.4f, qA, 0.6f * (slA + srn));
        float pB = fmaf(0.4f, qB, 0.6f * (slB + srn));
        float cA = __expf(pA - pself);
        float cB = __expf(pB - pself);
        denA += cA; denB += cB;
        accA0.x = fmaf(cA, a0.x, accA0.x); accA0.y = fmaf(cA, a0.y, accA0.y);
        accA0.z = fmaf(cA, a0.z, accA0.z); accA0.w = fmaf(cA, a0.w, accA0.w);
        accA1.x = fmaf(cA, a1.x, accA1.x); accA1.y = fmaf(cA, a1.y, accA1.y);
        accA1.z = fmaf(cA, a1.z, accA1.z); accA1.w = fmaf(cA, a1.w, accA1.w);
        accB0.x = fmaf(cB, b0.x, accB0.x); accB0.y = fmaf(cB, b0.y, accB0.y);
        accB0.z = fmaf(cB, b0.z, accB0.z); accB0.w = fmaf(cB, b0.w, accB0.w);
        accB1.x = fmaf(cB, b1.x, accB1.x); accB1.y = fmaf(cB, b1.y, accB1.y);
        accB1.z = fmaf(cB, b1.z, accB1.z); accB1.w = fmaf(cB, b1.w, accB1.w);
    }
    if (j < cnt) {
        int sA = colp[j];
        float slA = sl[sA];
        float4 a0 = *(const float4*)(xlb + sA * D);
        float4 a1 = *(const float4*)(xlb + sA * D + 4);
        float qA = absdot8(a0, a1, xr0, xr1, at0, at1);
#pragma unroll
        for (int o = LANES / 2; o > 0; o >>= 1) qA += __shfl_xor_sync(gmask, qA, o);
        float pA = fmaf(0.4f, qA, 0.6f * (slA + srn));
        float cA = __expf(pA - pself);
        denA += cA;
        accA0.x = fmaf(cA, a0.x, accA0.x); accA0.y = fmaf(cA, a0.y, accA0.y);
        accA0.z = fmaf(cA, a0.z, accA0.z); accA0.w = fmaf(cA, a0.w, accA0.w);
        accA1.x = fmaf(cA, a1.x, accA1.x); accA1.y = fmaf(cA, a1.y, accA1.y);
        accA1.z = fmaf(cA, a1.z, accA1.z); accA1.w = fmaf(cA, a1.w, accA1.w);
    }
    float inv = __fdividef(1.f, denA + denB);
    float4 bi0 = *(const float4*)(bias + l * 8);
    float4 bi1 = *(const float4*)(bias + l * 8 + 4);
    float4 o0, o1;
    o0.x = fmaf(accA0.x + accB0.x, inv, bi0.x);
    o0.y = fmaf(accA0.y + accB0.y, inv, bi0.y);
    o0.z = fmaf(accA0.z + accB0.z, inv, bi0.z);
    o0.w = fmaf(accA0.w + accB0.w, inv, bi0.w);
    o1.x = fmaf(accA1.x + accB1.x, inv, bi1.x);
    o1.y = fmaf(accA1.y + accB1.y, inv, bi1.y);
    o1.z = fmaf(accA1.z + accB1.z, inv, bi1.z);
    o1.w = fmaf(accA1.w + accB1.w, inv, bi1.w);
    if (RELU) {
        o0.x = fmaxf(o0.x, 0.f); o0.y = fmaxf(o0.y, 0.f);
        o0.z = fmaxf(o0.z, 0.f); o0.w = fmaxf(o0.w, 0.f);
        o1.x = fmaxf(o1.x, 0.f); o1.y = fmaxf(o1.y, 0.f);
        o1.z = fmaxf(o1.z, 0.f); o1.w = fmaxf(o1.w, 0.f);
    }
    *(float4*)(out + n * D + l * 8) = o0;
    *(float4*)(out + n * D + l * 8 + 4) = o1;
}

__global__ void gat1_kernel(const float* __restrict__ att, const float* __restrict__ bias) {
    gat_body<HID, 8, true>(g_xl, g_xr, g_sl1, g_sr1, att, bias, g_h);
}
__global__ void gat2_kernel(const float* __restrict__ att, const float* __restrict__ bias) {
    gat_body<OUTD, 4, false>(g_xl2, g_xr2, g_sl2, g_sr2, att, bias, g_ho);
}

// ---------------- layer-2 linear v6 + layer-2 node scores -----------------
#define HT_STRIDE 65
__global__ void __launch_bounds__(256) lin2_kernel(
        const float* __restrict__ Wl, const float* __restrict__ Wr,
        const float* __restrict__ bl, const float* __restrict__ br,
        const float* __restrict__ att2) {
    __shared__ __align__(16) float sW[2][HID * OUTD];
    __shared__ __align__(16) float shT[HID * HT_STRIDE];
    __shared__ float sat[OUTD];
    __shared__ float ssc[2][64];
    int tid = threadIdx.x;
    int nbase = blockIdx.x * 64;

    {
        const float4* wl4 = (const float4*)Wl;
        const float4* wr4 = (const float4*)Wr;
#pragma unroll
        for (int i = tid; i < HID * OUTD / 4; i += 256) {
            ((float4*)sW[0])[i] = wl4[i];
            ((float4*)sW[1])[i] = wr4[i];
        }
    }
    if (tid < OUTD) sat[tid] = att2[tid];
    {
        const float4* h4 = (const float4*)(g_h + nbase * HID);
#pragma unroll
        for (int i = tid; i < 64 * (HID / 4); i += 256) {
            int node = i >> 4, kq = i & 15;
            float4 v = h4[i];
            shT[(kq * 4 + 0) * HT_STRIDE + node] = v.x;
            shT[(kq * 4 + 1) * HT_STRIDE + node] = v.y;
            shT[(kq * 4 + 2) * HT_STRIDE + node] = v.z;
            shT[(kq * 4 + 3) * HT_STRIDE + node] = v.w;
        }
    }
    __syncthreads();

    int lane = tid & 31, wid = tid >> 5;
    int grp = wid & 1;
    int m = (wid >> 1) & 1;
    int half = wid >> 2;
    int node = nbase + grp * 32 + lane;

    const float* Wb = sW[m] + half * 16;
    const float* bp = (m ? br : bl) + half * 16;
    const float* hcol = shT + grp * 32 + lane;

    ull acc[8];
#pragma unroll
    for (int i = 0; i < 8; i++) acc[i] = *(const ull*)(bp + i * 2);

#pragma unroll 8
    for (int k = 0; k < HID; k++) {
        float hv = hcol[k * HT_STRIDE];
        ull h2 = bcast2(hv);
        const float* Wk = Wb + k * OUTD;
        longlong2 wa = *(const longlong2*)(Wk);
        longlong2 wb2 = *(const longlong2*)(Wk + 4);
        longlong2 wc = *(const longlong2*)(Wk + 8);
        longlong2 wd = *(const longlong2*)(Wk + 12);
        acc[0] = ffma2(h2, (ull)wa.x, acc[0]);
        acc[1] = ffma2(h2, (ull)wa.y, acc[1]);
        acc[2] = ffma2(h2, (ull)wb2.x, acc[2]);
        acc[3] = ffma2(h2, (ull)wb2.y, acc[3]);
        acc[4] = ffma2(h2, (ull)wc.x, acc[4]);
        acc[5] = ffma2(h2, (ull)wc.y, acc[5]);
        acc[6] = ffma2(h2, (ull)wd.x, acc[6]);
        acc[7] = ffma2(h2, (ull)wd.y, acc[7]);
    }

    float vals[16];
    float part = 0.f;
#pragma unroll
    for (int i = 0; i < 8; i++) {
        float lo = __uint_as_float((unsigned)acc[i]);
        float hi = __uint_as_float((unsigned)(acc[i] >> 32));
        vals[i * 2] = lo; vals[i * 2 + 1] = hi;
        part = fmaf(sat[half * 16 + i * 2], lo, part);
        part = fmaf(sat[half * 16 + i * 2 + 1], hi, part);
    }

    float* outp = (m ? g_xr2 : g_xl2) + node * OUTD + half * 16;
#pragma unroll
    for (int i = 0; i < 4; i++) {
        float4 v;
        v.x = vals[i * 4 + 0]; v.y = vals[i * 4 + 1];
        v.z = vals[i * 4 + 2]; v.w = vals[i * 4 + 3];
        *(float4*)(outp + i * 4) = v;
    }

    if (half == 0) ssc[m][grp * 32 + lane] = part;
    __syncthreads();
    if (half == 1) {
        float tot = part + ssc[m][grp * 32 + lane];
        if (m) g_sr2[node] = tot; else g_sl2[node] = tot;
    }
}

// ---------------- sim = h1 @ h2^T per batch (64-row tiles) + stats --------
__global__ void sim_kernel() {
    __shared__ __align__(16) float sh[32 * 68];
    int b = blockIdx.y, tile = blockIdx.x;
    int tid = threadIdx.x;
    const float* h1 = g_ho + b * NN * OUTD;
    const float* h2 = g_ho + NTOT * OUTD + b * NN * OUTD;

    for (int idx = tid; idx < 64 * 32; idx += 256) {
        int nloc = idx >> 5, k = idx & 31;
        sh[k * 68 + nloc] = h1[(tile * 64 + nloc) * OUTD + k];
    }
    __syncthreads();

    int m = tid;
    float b2[32];
#pragma unroll
    for (int k = 0; k < 32; k++) b2[k] = h2[m * OUTD + k];

    float fsum = 0.f, fsq = 0.f;
    float lmin = FLT_MAX, lmax = -FLT_MAX;
    float* simb = g_sim + b * NEL;

    for (int g = 0; g < 16; g++) {
        int n0 = g * 4;
        float c0 = 0.f, c1 = 0.f, c2 = 0.f, c3 = 0.f;
#pragma unroll
        for (int k = 0; k < 32; k++) {
            float4 qv = *(const float4*)&sh[k * 68 + n0];
            float w = b2[k];
            c0 = fmaf(qv.x, w, c0);
            c1 = fmaf(qv.y, w, c1);
            c2 = fmaf(qv.z, w, c2);
            c3 = fmaf(qv.w, w, c3);
        }
        int nn = tile * 64 + n0;
        simb[(nn + 0) * NN + m] = c0;
        simb[(nn + 1) * NN + m] = c1;
        simb[(nn + 2) * NN + m] = c2;
        simb[(nn + 3) * NN + m] = c3;
        fsum += (c0 + c1) + (c2 + c3);
        fsq = fmaf(c0, c0, fsq); fsq = fmaf(c1, c1, fsq);
        fsq = fmaf(c2, c2, fsq); fsq = fmaf(c3, c3, fsq);
        lmin = fminf(lmin, fminf(fminf(c0, c1), fminf(c2, c3)));
        lmax = fmaxf(lmax, fmaxf(fmaxf(c0, c1), fmaxf(c2, c3)));
    }
#pragma unroll
    for (int o = 16; o > 0; o >>= 1) {
        fsum += __shfl_xor_sync(0xffffffffu, fsum, o);
        fsq += __shfl_xor_sync(0xffffffffu, fsq, o);
        lmin = fminf(lmin, __shfl_xor_sync(0xffffffffu, lmin, o));
        lmax = fmaxf(lmax, __shfl_xor_sync(0xffffffffu, lmax, o));
    }
    if ((tid & 31) == 0) {
        atomicAdd(&g_sum[b], fsum);
        atomicAdd(&g_sumsq[b], fsq);
        atomicMin(&g_minkey[b], f2key(lmin));
        atomicMax(&g_maxkey[b], f2key(lmax));
    }
}

// ---------------- fused Sinkhorn with exp-cache ----------------------------
// pass0: E=exp(-(A*sim+C)); S_t = sum 1/(1+E*exp(-s_t)); out=min(1,inv*sig)
__global__ void sinkhorn_kernel(float* __restrict__ out,
                                const float* __restrict__ gamma,
                                const float* __restrict__ beta) {
    __shared__ float shAC[2];
    __shared__ float shS;
    __shared__ float red[8];
    int b = blockIdx.y, tid = threadIdx.x;
    if (tid == 0) {
        double mu = (double)g_sum[b] / (double)NEL;
        double var = (double)g_sumsq[b] / (double)NEL - mu * mu;
        if (var < 0.0) var = 0.0;
        float r = (float)(1.0 / sqrt(var + 1e-5));
        float sc = gamma[0] * r;
        float off = beta[0] - sc * (float)mu;
        float v1 = sc * key2f(g_minkey[b]) + off;
        float v2 = sc * key2f(g_maxkey[b]) + off;
        float mn = fminf(v1, v2), mx = fmaxf(v1, v2);
        shAC[0] = 2.f * sc;              // TAU = 1
        shAC[1] = 2.f * off - mn - mx;
    }
    __syncthreads();
    float A = shAC[0], C = shAC[1];

    size_t base = (size_t)b * NEL + blockIdx.x * (NEL / SPLIT);
    const float4* simv = (const float4*)(g_sim + base);
    float4* Ev = (float4*)(g_E + base);
    const float nF = (float)NEL, kF = (float)NN;
    const float logc = logf(kF / (nF - kF));
    float s = 0.f, S = 0.f;

#pragma unroll
    for (int t = 0; t < 5; t++) {
        float acc = 0.f;
        if (t == 0) {
            for (int j = tid; j < NEL / SPLIT / 4; j += 256) {
                float4 v = simv[j];
                float4 e;
                e.x = __expf(-fmaf(A, v.x, C));
                e.y = __expf(-fmaf(A, v.y, C));
                e.z = __expf(-fmaf(A, v.z, C));
                e.w = __expf(-fmaf(A, v.w, C));
                Ev[j] = e;
                acc += __fdividef(1.f, 1.f + e.x);
                acc += __fdividef(1.f, 1.f + e.y);
                acc += __fdividef(1.f, 1.f + e.z);
                acc += __fdividef(1.f, 1.f + e.w);
            }
        } else {
            float q = __expf(-s);
            for (int j = tid; j < NEL / SPLIT / 4; j += 256) {
                float4 e = Ev[j];
                acc += __fdividef(1.f, fmaf(e.x, q, 1.f));
                acc += __fdividef(1.f, fmaf(e.y, q, 1.f));
                acc += __fdividef(1.f, fmaf(e.z, q, 1.f));
                acc += __fdividef(1.f, fmaf(e.w, q, 1.f));
            }
        }
#pragma unroll
        for (int o = 16; o > 0; o >>= 1) acc += __shfl_xor_sync(0xffffffffu, acc, o);
        if ((tid & 31) == 0) red[tid >> 5] = acc;
        __syncthreads();
        if (tid == 0) {
            float x = red[0];
#pragma unroll
            for (int w = 1; w < 8; w++) x += red[w];
            atomicAdd(&g_S[t][b], x);
            __threadfence();
            atomicAdd(&g_arr[t][b], 1);
            while (*(volatile int*)&g_arr[t][b] != SPLIT) { }
            __threadfence();
            shS = g_S[t][b];
        }
        __syncthreads();
        S = shS;
        if (t < 4) s += __logf((nF - S) / S) + logc;
        __syncthreads();
    }
    float inv = kF / S;
    float q = __expf(-s);
    float4* outv = (float4*)(out + base);
    for (int j = tid; j < NEL / SPLIT / 4; j += 256) {
        float4 e = Ev[j];
        float4 o;
        o.x = fminf(1.f, inv * __fdividef(1.f, fmaf(e.x, q, 1.f)));
        o.y = fminf(1.f, inv * __fdividef(1.f, fmaf(e.y, q, 1.f)));
        o.z = fminf(1.f, inv * __fdividef(1.f, fmaf(e.z, q, 1.f)));
        o.w = fminf(1.f, inv * __fdividef(1.f, fmaf(e.w, q, 1.f)));
        outv[j] = o;
    }
}

// ---------------- launch ----------------
extern "C" void kernel_launch(void* const* d_in, const int* in_sizes, int n_in,
                              void* d_out, int out_size) {
    const float* x1 = (const float*)d_in[0];
    const float* x2 = (const float*)d_in[1];
    const void* e1 = d_in[2];
    const void* e2 = d_in[3];
    const float* Wl1 = (const float*)d_in[4];
    const float* Wr1 = (const float*)d_in[5];
    const float* bl1 = (const float*)d_in[6];
    const float* br1 = (const float*)d_in[7];
    const float* att1 = (const float*)d_in[8];
    const float* bias1 = (const float*)d_in[9];
    const float* Wl2 = (const float*)d_in[10];
    const float* Wr2 = (const float*)d_in[11];
    const float* bl2 = (const float*)d_in[12];
    const float* br2 = (const float*)d_in[13];
    const float* att2 = (const float*)d_in[14];
    const float* bias2 = (const float*)d_in[15];
    const float* gamma = (const float*)d_in[16];
    const float* beta = (const float*)d_in[17];

    setup_kernel<<<(NT2 + 255) / 256, 256>>>((const int*)e1);
    scatlin_kernel<<<SCAT_BLOCKS + LIN1_BLOCKS, 256>>>(e1, e2, x1, x2, Wl1, Wr1, bl1, br1, att1);
    gat1_kernel<<<NT2 / 4 / 8, 256>>>(att1, bias1);
    lin2_kernel<<<NT2 / 64, 256>>>(Wl2, Wr2, bl2, br2, att2);
    gat2_kernel<<<NT2 / 8 / 8, 256>>>(att2, bias2);
    sim_kernel<<<dim3(4, BB), 256>>>();
    sinkhorn_kernel<<<dim3(SPLIT, BB), 256>>>((float*)d_out, gamma, beta);
}

// round 15
// speedup vs baseline: 1.0830x; 1.0830x over previous
#include <cuda_runtime.h>
#include <math.h>
#include <float.h>

#define NTOT 16384
#define NT2  (2 * NTOT)
#define BB 64
#define NN 256
#define IND 7
#define HID 64
#define OUTD 32
#define EE 524288
#define ADJ 96
#define NEL 65536
#define SPLIT 8
#define NB 4096
#define SCAT_BLOCKS (2 * EE / 256)
#define LIN1_BLOCKS (NT2 * HID / 256)

typedef unsigned long long ull;

// ---------------- scratch ----------------
__device__ float g_xl[NT2 * HID];
__device__ float g_xr[NT2 * HID];
__device__ float g_h[NT2 * HID];
__device__ float g_xl2[NT2 * OUTD];
__device__ float g_xr2[NT2 * OUTD];
__device__ float g_ho[NT2 * OUTD];
__device__ int g_cnt[NT2];
__device__ int g_adj[NT2 * ADJ];
__device__ float g_sim[BB * NEL];
__device__ unsigned g_hist[BB * NB];
__device__ float g_sum[BB], g_sumsq[BB];
__device__ unsigned g_minkey[BB], g_maxkey[BB];
__device__ float g_s4[BB], g_S4[BB];
__device__ int g_is64;

// ---------------- helpers ----------------
__device__ __forceinline__ unsigned f2key(float f) {
    unsigned u = __float_as_uint(f);
    return (u & 0x80000000u) ? ~u : (u | 0x80000000u);
}
__device__ __forceinline__ float key2f(unsigned k) {
    unsigned u = (k & 0x80000000u) ? (k ^ 0x80000000u) : ~k;
    return __uint_as_float(u);
}
__device__ __forceinline__ float sigf(float x) {
    return __fdividef(1.f, 1.f + __expf(-x));
}
__device__ __forceinline__ ull ffma2(ull a, ull b, ull c) {
    ull d;
    asm("fma.rn.f32x2 %0, %1, %2, %3;" : "=l"(d) : "l"(a), "l"(b), "l"(c));
    return d;
}
__device__ __forceinline__ ull bcast2(float x) {
    ull d;
    asm("mov.b64 %0, {%1, %1};" : "=l"(d) : "f"(x));
    return d;
}
// per-batch affine d = A*sim + C (from instance-norm stats + min/max)
__device__ __forceinline__ void compute_AC(int b, const float* gamma, const float* beta,
                                           float& A, float& C, float& mn, float& mx) {
    double mu = (double)g_sum[b] / (double)NEL;
    double var = (double)g_sumsq[b] / (double)NEL - mu * mu;
    if (var < 0.0) var = 0.0;
    float r = (float)(1.0 / sqrt(var + 1e-5));
    float sc = gamma[0] * r;
    float off = beta[0] - sc * (float)mu;
    mn = key2f(g_minkey[b]);
    mx = key2f(g_maxkey[b]);
    float v1 = sc * mn + off;
    float v2 = sc * mx + off;
    float dmn = fminf(v1, v2), dmx = fmaxf(v1, v2);
    A = 2.f * sc;                   // TAU = 1
    C = 2.f * off - dmn - dmx;
}

// ---------------- setup ----------------
__global__ void setup_kernel(const int* __restrict__ e1w) {
    int t = blockIdx.x * blockDim.x + threadIdx.x;
    if (t < NT2) {
        g_cnt[t] = 1;
        g_adj[t * ADJ] = t;   // self loop first
    }
#pragma unroll
    for (int i = t; i < BB * NB; i += NT2) g_hist[i] = 0u;
    if (t < BB) {
        g_sum[t] = 0.f;
        g_sumsq[t] = 0.f;
        g_minkey[t] = 0xFFFFFFFFu;
        g_maxkey[t] = 0u;
    }
    if (t == 0) {
        int any = 0;
#pragma unroll
        for (int i = 0; i < 64; i++) any |= e1w[2 * i + 1];
        g_is64 = (any == 0) ? 1 : 0;
    }
}

// ---------------- scatter + lin1 fused (round-13 proven version) ----------
__global__ void scatlin_kernel(const void* __restrict__ e1, const void* __restrict__ e2,
                               const float* __restrict__ x1, const float* __restrict__ x2,
                               const float* __restrict__ Wl, const float* __restrict__ Wr,
                               const float* __restrict__ bl, const float* __restrict__ br) {
    int gb = blockIdx.x;
    int tid = threadIdx.x;
    if (gb < SCAT_BLOCKS) {
        int e = gb * 256 + tid;
        int side = (e >= EE);
        int le = e - side * EE;
        const void* ep = side ? e2 : e1;
        int src, dst;
        if (g_is64) {
            const long long* p = (const long long*)ep;
            src = (int)p[le];
            dst = (int)p[EE + le];
        } else {
            const int* p = (const int*)ep;
            src = p[le];
            dst = p[EE + le];
        }
        int n = side * NTOT + dst;
        int pos = atomicAdd(&g_cnt[n], 1);
        if (pos < ADJ) g_adj[n * ADJ + pos] = side * NTOT + src;
    } else {
        int gid = (gb - SCAT_BLOCKS) * 256 + tid;
        int n = gid >> 6, d = gid & 63;
        const float* x = (n >= NTOT) ? (x2 + (n - NTOT) * IND) : (x1 + n * IND);
        float a = bl[d], b = br[d];
#pragma unroll
        for (int k = 0; k < IND; k++) {
            float xv = x[k];
            a = fmaf(xv, Wl[k * HID + d], a);
            b = fmaf(xv, Wr[k * HID + d], b);
        }
        g_xl[gid] = a;
        g_xr[gid] = b;
    }
}

// ---------------- GATv2: global gather, lane owns 8 elems (round 13) ------
__device__ __forceinline__ float dot8(float4 a0, float4 a1, float4 xr0, float4 xr1,
                                      float4 at0, float4 at1) {
    float zx = a0.x + xr0.x, zy = a0.y + xr0.y, zz = a0.z + xr0.z, zw = a0.w + xr0.w;
    zx = fmaxf(zx, 0.2f * zx); zy = fmaxf(zy, 0.2f * zy);
    zz = fmaxf(zz, 0.2f * zz); zw = fmaxf(zw, 0.2f * zw);
    float p = at0.x * zx;
    p = fmaf(at0.y, zy, p); p = fmaf(at0.z, zz, p); p = fmaf(at0.w, zw, p);
    zx = a1.x + xr1.x; zy = a1.y + xr1.y; zz = a1.z + xr1.z; zw = a1.w + xr1.w;
    zx = fmaxf(zx, 0.2f * zx); zy = fmaxf(zy, 0.2f * zy);
    zz = fmaxf(zz, 0.2f * zz); zw = fmaxf(zw, 0.2f * zw);
    p = fmaf(at1.x, zx, p); p = fmaf(at1.y, zy, p);
    p = fmaf(at1.z, zz, p); p = fmaf(at1.w, zw, p);
    return p;
}

template <int D, int LANES, bool RELU>
__device__ __forceinline__ void gat_body(const float* __restrict__ xl,
                                         const float* __restrict__ xr,
                                         const float* __restrict__ att,
                                         const float* __restrict__ bias,
                                         float* __restrict__ out) {
    constexpr int GP = 32 / LANES;
    int warp = (blockIdx.x * blockDim.x + threadIdx.x) >> 5;
    int lane = threadIdx.x & 31;
    int sub = lane / LANES;
    int l = lane % LANES;
    int n = warp * GP + sub;
    if (n >= NT2) return;
    unsigned gmask = ((1u << LANES) - 1u) << (sub * LANES);

    const float* xlb = xl + l * 8;
    const float* xrb = xr + n * D + l * 8;
    float4 xr0 = *(const float4*)(xrb);
    float4 xr1 = *(const float4*)(xrb + 4);
    float4 at0 = *(const float4*)(att + l * 8);
    float4 at1 = *(const float4*)(att + l * 8 + 4);

    // self loop (score shift reference)
    float4 s0 = *(const float4*)(xlb + n * D);
    float4 s1 = *(const float4*)(xlb + n * D + 4);
    float p = dot8(s0, s1, xr0, xr1, at0, at1);
#pragma unroll
    for (int o = LANES / 2; o > 0; o >>= 1) p += __shfl_xor_sync(gmask, p, o);
    float pself = p;

    float4 accA0 = s0, accA1 = s1; float denA = 1.f;
    float4 accB0 = make_float4(0.f, 0.f, 0.f, 0.f), accB1 = accB0; float denB = 0.f;

    int cnt = g_cnt[n];
    if (cnt > ADJ) cnt = ADJ;
    const int* colp = g_adj + n * ADJ;
    int j = 1;
    for (; j + 1 < cnt; j += 2) {
        int sA = colp[j], sB = colp[j + 1];
        float4 a0 = *(const float4*)(xlb + sA * D);
        float4 a1 = *(const float4*)(xlb + sA * D + 4);
        float4 b0 = *(const float4*)(xlb + sB * D);
        float4 b1 = *(const float4*)(xlb + sB * D + 4);
        float pA = dot8(a0, a1, xr0, xr1, at0, at1);
        float pB = dot8(b0, b1, xr0, xr1, at0, at1);
#pragma unroll
        for (int o = LANES / 2; o > 0; o >>= 1) {
            pA += __shfl_xor_sync(gmask, pA, o);
            pB += __shfl_xor_sync(gmask, pB, o);
        }
        float cA = __expf(pA - pself);
        float cB = __expf(pB - pself);
        denA += cA; denB += cB;
        accA0.x = fmaf(cA, a0.x, accA0.x); accA0.y = fmaf(cA, a0.y, accA0.y);
        accA0.z = fmaf(cA, a0.z, accA0.z); accA0.w = fmaf(cA, a0.w, accA0.w);
        accA1.x = fmaf(cA, a1.x, accA1.x); accA1.y = fmaf(cA, a1.y, accA1.y);
        accA1.z = fmaf(cA, a1.z, accA1.z); accA1.w = fmaf(cA, a1.w, accA1.w);
        accB0.x = fmaf(cB, b0.x, accB0.x); accB0.y = fmaf(cB, b0.y, accB0.y);
        accB0.z = fmaf(cB, b0.z, accB0.z); accB0.w = fmaf(cB, b0.w, accB0.w);
        accB1.x = fmaf(cB, b1.x, accB1.x); accB1.y = fmaf(cB, b1.y, accB1.y);
        accB1.z = fmaf(cB, b1.z, accB1.z); accB1.w = fmaf(cB, b1.w, accB1.w);
    }
    if (j < cnt) {
        int sA = colp[j];
        float4 a0 = *(const float4*)(xlb + sA * D);
        float4 a1 = *(const float4*)(xlb + sA * D + 4);
        float pA = dot8(a0, a1, xr0, xr1, at0, at1);
#pragma unroll
        for (int o = LANES / 2; o > 0; o >>= 1) pA += __shfl_xor_sync(gmask, pA, o);
        float cA = __expf(pA - pself);
        denA += cA;
        accA0.x = fmaf(cA, a0.x, accA0.x); accA0.y = fmaf(cA, a0.y, accA0.y);
        accA0.z = fmaf(cA, a0.z, accA0.z); accA0.w = fmaf(cA, a0.w, accA0.w);
        accA1.x = fmaf(cA, a1.x, accA1.x); accA1.y = fmaf(cA, a1.y, accA1.y);
        accA1.z = fmaf(cA, a1.z, accA1.z); accA1.w = fmaf(cA, a1.w, accA1.w);
    }
    float inv = __fdividef(1.f, denA + denB);
    float4 bi0 = *(const float4*)(bias + l * 8);
    float4 bi1 = *(const float4*)(bias + l * 8 + 4);
    float4 o0, o1;
    o0.x = fmaf(accA0.x + accB0.x, inv, bi0.x);
    o0.y = fmaf(accA0.y + accB0.y, inv, bi0.y);
    o0.z = fmaf(accA0.z + accB0.z, inv, bi0.z);
    o0.w = fmaf(accA0.w + accB0.w, inv, bi0.w);
    o1.x = fmaf(accA1.x + accB1.x, inv, bi1.x);
    o1.y = fmaf(accA1.y + accB1.y, inv, bi1.y);
    o1.z = fmaf(accA1.z + accB1.z, inv, bi1.z);
    o1.w = fmaf(accA1.w + accB1.w, inv, bi1.w);
    if (RELU) {
        o0.x = fmaxf(o0.x, 0.f); o0.y = fmaxf(o0.y, 0.f);
        o0.z = fmaxf(o0.z, 0.f); o0.w = fmaxf(o0.w, 0.f);
        o1.x = fmaxf(o1.x, 0.f); o1.y = fmaxf(o1.y, 0.f);
        o1.z = fmaxf(o1.z, 0.f); o1.w = fmaxf(o1.w, 0.f);
    }
    *(float4*)(out + n * D + l * 8) = o0;
    *(float4*)(out + n * D + l * 8 + 4) = o1;
}

__global__ void gat1_kernel(const float* __restrict__ att, const float* __restrict__ bias) {
    gat_body<HID, 8, true>(g_xl, g_xr, att, bias, g_h);
}
__global__ void gat2_kernel(const float* __restrict__ att, const float* __restrict__ bias) {
    gat_body<OUTD, 4, false>(g_xl2, g_xr2, att, bias, g_ho);
}

// ---------------- layer-2 linear v6: broadcast weights (round 13) ---------
#define HT_STRIDE 65
__global__ void __launch_bounds__(256) lin2_kernel(
        const float* __restrict__ Wl, const float* __restrict__ Wr,
        const float* __restrict__ bl, const float* __restrict__ br) {
    __shared__ __align__(16) float sW[2][HID * OUTD];
    __shared__ __align__(16) float shT[HID * HT_STRIDE];
    int tid = threadIdx.x;
    int nbase = blockIdx.x * 64;

    {
        const float4* wl4 = (const float4*)Wl;
        const float4* wr4 = (const float4*)Wr;
#pragma unroll
        for (int i = tid; i < HID * OUTD / 4; i += 256) {
            ((float4*)sW[0])[i] = wl4[i];
            ((float4*)sW[1])[i] = wr4[i];
        }
    }
    {
        const float4* h4 = (const float4*)(g_h + nbase * HID);
#pragma unroll
        for (int i = tid; i < 64 * (HID / 4); i += 256) {
            int node = i >> 4, kq = i & 15;
            float4 v = h4[i];
            shT[(kq * 4 + 0) * HT_STRIDE + node] = v.x;
            shT[(kq * 4 + 1) * HT_STRIDE + node] = v.y;
            shT[(kq * 4 + 2) * HT_STRIDE + node] = v.z;
            shT[(kq * 4 + 3) * HT_STRIDE + node] = v.w;
        }
    }
    __syncthreads();

    int lane = tid & 31, wid = tid >> 5;
    int grp = wid & 1;
    int m = (wid >> 1) & 1;
    int half = wid >> 2;
    int node = nbase + grp * 32 + lane;

    const float* Wb = sW[m] + half * 16;
    const float* bp = (m ? br : bl) + half * 16;
    const float* hcol = shT + grp * 32 + lane;

    ull acc[8];
#pragma unroll
    for (int i = 0; i < 8; i++) acc[i] = *(const ull*)(bp + i * 2);

#pragma unroll 8
    for (int k = 0; k < HID; k++) {
        float hv = hcol[k * HT_STRIDE];
        ull h2 = bcast2(hv);
        const float* Wk = Wb + k * OUTD;
        longlong2 wa = *(const longlong2*)(Wk);
        longlong2 wb2 = *(const longlong2*)(Wk + 4);
        longlong2 wc = *(const longlong2*)(Wk + 8);
        longlong2 wd = *(const longlong2*)(Wk + 12);
        acc[0] = ffma2(h2, (ull)wa.x, acc[0]);
        acc[1] = ffma2(h2, (ull)wa.y, acc[1]);
        acc[2] = ffma2(h2, (ull)wb2.x, acc[2]);
        acc[3] = ffma2(h2, (ull)wb2.y, acc[3]);
        acc[4] = ffma2(h2, (ull)wc.x, acc[4]);
        acc[5] = ffma2(h2, (ull)wc.y, acc[5]);
        acc[6] = ffma2(h2, (ull)wd.x, acc[6]);
        acc[7] = ffma2(h2, (ull)wd.y, acc[7]);
    }

    float* outp = (m ? g_xr2 : g_xl2) + node * OUTD + half * 16;
#pragma unroll
    for (int i = 0; i < 4; i++) {
        float4 v;
        v.x = __uint_as_float((unsigned)(acc[i * 2]));
        v.y = __uint_as_float((unsigned)(acc[i * 2] >> 32));
        v.z = __uint_as_float((unsigned)(acc[i * 2 + 1]));
        v.w = __uint_as_float((unsigned)(acc[i * 2 + 1] >> 32));
        *(float4*)(outp + i * 4) = v;
    }
}

// ---------------- sim = h1 @ h2^T per batch (64-row tiles) + stats --------
__global__ void sim_kernel() {
    __shared__ __align__(16) float sh[32 * 68];
    int b = blockIdx.y, tile = blockIdx.x;
    int tid = threadIdx.x;
    const float* h1 = g_ho + b * NN * OUTD;
    const float* h2 = g_ho + NTOT * OUTD + b * NN * OUTD;

    for (int idx = tid; idx < 64 * 32; idx += 256) {
        int nloc = idx >> 5, k = idx & 31;
        sh[k * 68 + nloc] = h1[(tile * 64 + nloc) * OUTD + k];
    }
    __syncthreads();

    int m = tid;
    float b2[32];
#pragma unroll
    for (int k = 0; k < 32; k++) b2[k] = h2[m * OUTD + k];

    float fsum = 0.f, fsq = 0.f;
    float lmin = FLT_MAX, lmax = -FLT_MAX;
    float* simb = g_sim + b * NEL;

    for (int g = 0; g < 16; g++) {
        int n0 = g * 4;
        float c0 = 0.f, c1 = 0.f, c2 = 0.f, c3 = 0.f;
#pragma unroll
        for (int k = 0; k < 32; k++) {
            float4 q = *(const float4*)&sh[k * 68 + n0];
            float w = b2[k];
            c0 = fmaf(q.x, w, c0);
            c1 = fmaf(q.y, w, c1);
            c2 = fmaf(q.z, w, c2);
            c3 = fmaf(q.w, w, c3);
        }
        int nn = tile * 64 + n0;
        simb[(nn + 0) * NN + m] = c0;
        simb[(nn + 1) * NN + m] = c1;
        simb[(nn + 2) * NN + m] = c2;
        simb[(nn + 3) * NN + m] = c3;
        fsum += (c0 + c1) + (c2 + c3);
        fsq = fmaf(c0, c0, fsq); fsq = fmaf(c1, c1, fsq);
        fsq = fmaf(c2, c2, fsq); fsq = fmaf(c3, c3, fsq);
        lmin = fminf(lmin, fminf(fminf(c0, c1), fminf(c2, c3)));
        lmax = fmaxf(lmax, fmaxf(fmaxf(c0, c1), fmaxf(c2, c3)));
    }
#pragma unroll
    for (int o = 16; o > 0; o >>= 1) {
        fsum += __shfl_xor_sync(0xffffffffu, fsum, o);
        fsq += __shfl_xor_sync(0xffffffffu, fsq, o);
        lmin = fminf(lmin, __shfl_xor_sync(0xffffffffu, lmin, o));
        lmax = fmaxf(lmax, __shfl_xor_sync(0xffffffffu, lmax, o));
    }
    if ((tid & 31) == 0) {
        atomicAdd(&g_sum[b], fsum);
        atomicAdd(&g_sumsq[b], fsq);
        atomicMin(&g_minkey[b], f2key(lmin));
        atomicMax(&g_maxkey[b], f2key(lmax));
    }
}

// ---------------- Sinkhorn stage 1: per-batch histogram of sim ------------
__global__ void sk_hist_kernel() {
    __shared__ unsigned hcnt[NB];
    __shared__ float shmn, shscale;
    int b = blockIdx.y, tid = threadIdx.x;
    for (int i = tid; i < NB; i += 256) hcnt[i] = 0u;
    if (tid == 0) {
        float mn = key2f(g_minkey[b]);
        float mx = key2f(g_maxkey[b]);
        shmn = mn;
        shscale = (mx > mn) ? ((float)NB / (mx - mn)) : 0.f;
    }
    __syncthreads();
    float mn = shmn, scale = shscale;
    const float4* simv = (const float4*)(g_sim + (size_t)b * NEL + blockIdx.x * (NEL / SPLIT));
    for (int j = tid; j < NEL / SPLIT / 4; j += 256) {
        float4 v = simv[j];
        int b0 = min(NB - 1, (int)((v.x - mn) * scale));
        int b1 = min(NB - 1, (int)((v.y - mn) * scale));
        int b2 = min(NB - 1, (int)((v.z - mn) * scale));
        int b3 = min(NB - 1, (int)((v.w - mn) * scale));
        atomicAdd(&hcnt[b0], 1u);
        atomicAdd(&hcnt[b1], 1u);
        atomicAdd(&hcnt[b2], 1u);
        atomicAdd(&hcnt[b3], 1u);
    }
    __syncthreads();
    for (int i = tid; i < NB; i += 256) {
        unsigned c = hcnt[i];
        if (c) atomicAdd(&g_hist[b * NB + i], c);
    }
}

// ---------------- Sinkhorn stage 2: 5 iterations on the histogram ---------
__global__ void sk_solve_kernel(const float* __restrict__ gamma,
                                const float* __restrict__ beta) {
    __shared__ float red[8];
    __shared__ float shs, shS;
    __shared__ float shp[4];   // A, C, mn, binw
    int b = blockIdx.x, tid = threadIdx.x;
    if (tid == 0) {
        float A, C, mn, mx;
        compute_AC(b, gamma, beta, A, C, mn, mx);
        shp[0] = A; shp[1] = C; shp[2] = mn;
        shp[3] = (mx - mn) / (float)NB;
    }
    __syncthreads();
    float A = shp[0], C = shp[1], mn = shp[2], binw = shp[3];

    // each thread owns 16 bins
    float cntv[NB / 256];
    float dv[NB / 256];
#pragma unroll
    for (int i = 0; i < NB / 256; i++) {
        int bin = tid + i * 256;
        cntv[i] = (float)g_hist[b * NB + bin];
        float v = mn + ((float)bin + 0.5f) * binw;
        dv[i] = fmaf(A, v, C);
    }

    const float nF = (float)NEL, kF = (float)NN;
    const float logc = logf(kF / (nF - kF));
    float s = 0.f, S = 0.f;
#pragma unroll
    for (int t = 0; t < 5; t++) {
        float acc = 0.f;
#pragma unroll
        for (int i = 0; i < NB / 256; i++)
            acc += cntv[i] * sigf(dv[i] + s);
#pragma unroll
        for (int o = 16; o > 0; o >>= 1) acc += __shfl_xor_sync(0xffffffffu, acc, o);
        if ((tid & 31) == 0) red[tid >> 5] = acc;
        __syncthreads();
        if (tid == 0) {
            float x = red[0];
#pragma unroll
            for (int w = 1; w < 8; w++) x += red[w];
            shS = x;
        }
        __syncthreads();
        S = shS;
        if (t < 4) s += logf((nF - S) / S) + logc;
        __syncthreads();
    }
    if (tid == 0) {
        g_s4[b] = s;
        g_S4[b] = S;
    }
}

// ---------------- Sinkhorn stage 3: output pass ----------------------------
__global__ void sk_out_kernel(float* __restrict__ out,
                              const float* __restrict__ gamma,
                              const float* __restrict__ beta) {
    __shared__ float shp[3];   // A, xo, inv
    int b = blockIdx.y, tid = threadIdx.x;
    if (tid == 0) {
        float A, C, mn, mx;
        compute_AC(b, gamma, beta, A, C, mn, mx);
        shp[0] = A;
        shp[1] = C + g_s4[b];
        shp[2] = (float)NN / g_S4[b];
    }
    __syncthreads();
    float A = shp[0], xo = shp[1], inv = shp[2];
    size_t base = (size_t)b * NEL + blockIdx.x * (NEL / SPLIT);
    const float4* simv = (const float4*)(g_sim + base);
    float4* outv = (float4*)(out + base);
    for (int j = tid; j < NEL / SPLIT / 4; j += 256) {
        float4 v = simv[j];
        float4 o;
        o.x = fminf(1.f, inv * sigf(fmaf(A, v.x, xo)));
        o.y = fminf(1.f, inv * sigf(fmaf(A, v.y, xo)));
        o.z = fminf(1.f, inv * sigf(fmaf(A, v.z, xo)));
        o.w = fminf(1.f, inv * sigf(fmaf(A, v.w, xo)));
        outv[j] = o;
    }
}

// ---------------- launch ----------------
extern "C" void kernel_launch(void* const* d_in, const int* in_sizes, int n_in,
                              void* d_out, int out_size) {
    const float* x1 = (const float*)d_in[0];
    const float* x2 = (const float*)d_in[1];
    const void* e1 = d_in[2];
    const void* e2 = d_in[3];
    const float* Wl1 = (const float*)d_in[4];
    const float* Wr1 = (const float*)d_in[5];
    const float* bl1 = (const float*)d_in[6];
    const float* br1 = (const float*)d_in[7];
    const float* att1 = (const float*)d_in[8];
    const float* bias1 = (const float*)d_in[9];
    const float* Wl2 = (const float*)d_in[10];
    const float* Wr2 = (const float*)d_in[11];
    const float* bl2 = (const float*)d_in[12];
    const float* br2 = (const float*)d_in[13];
    const float* att2 = (const float*)d_in[14];
    const float* bias2 = (const float*)d_in[15];
    const float* gamma = (const float*)d_in[16];
    const float* beta = (const float*)d_in[17];

    setup_kernel<<<(NT2 + 255) / 256, 256>>>((const int*)e1);
    scatlin_kernel<<<SCAT_BLOCKS + LIN1_BLOCKS, 256>>>(e1, e2, x1, x2, Wl1, Wr1, bl1, br1);
    gat1_kernel<<<NT2 / 4 / 8, 256>>>(att1, bias1);
    lin2_kernel<<<NT2 / 64, 256>>>(Wl2, Wr2, bl2, br2);
    gat2_kernel<<<NT2 / 8 / 8, 256>>>(att2, bias2);
    sim_kernel<<<dim3(4, BB), 256>>>();
    sk_hist_kernel<<<dim3(SPLIT, BB), 256>>>();
    sk_solve_kernel<<<BB, 256>>>(gamma, beta);
    sk_out_kernel<<<dim3(SPLIT, BB), 256>>>((float*)d_out, gamma, beta);
}